// round 11
// baseline (speedup 1.0000x reference)
#include <cuda_runtime.h>
#include <cstdint>

// ---------------- problem constants ----------------
#define NDST0  100000
#define NDST1  20000
#define NDST2  4096
#define NE0    1000000
#define NE1    300000
#define NE2    61440
#define D_IN   128
#define D_H    256
#define D_OUT  47

#define NB0 ((NDST0 + 255) / 256)   // 391
#define NB1 ((NDST1 + 255) / 256)   // 79
#define NB2 ((NDST2 + 255) / 256)   // 16
#define NBT (NB0 + NB1 + NB2)       // 486
#define ETOT (NE0 + NE1 + NE2)      // 1361440
#define NTOT (NDST0 + NDST1 + NDST2)

// ---------------- scratch (device globals: allocation-free) ----------------
__device__ float g_agg0[(size_t)NDST0 * D_IN];
__device__ float g_h1[(size_t)NDST0 * D_H];
__device__ float g_agg1[(size_t)NDST1 * D_H];
__device__ float g_h2[(size_t)NDST1 * D_H];
__device__ float g_agg2[(size_t)NDST2 * D_H];
// per-layer CSR buffers
__device__ int g_cnt0[NDST0];
__device__ int g_cnt1[NDST1];
__device__ int g_cnt2[NDST2];
__device__ int g_rp0[NDST0 + 1];
__device__ int g_rp1[NDST1 + 1];
__device__ int g_rp2[NDST2 + 1];
__device__ int g_cur0[NDST0];
__device__ int g_cur1[NDST1];
__device__ int g_cur2[NDST2];
__device__ int g_eidx0[NE0];
__device__ int g_eidx1[NE1];
__device__ int g_eidx2[NE2];
__device__ int g_bsum0[NB0];
__device__ int g_bsum1[NB1];
__device__ int g_bsum2[NB2];
// transposed/concat weights: Bt[n][k2] = (k2<K ? Ws[k2][n] : Wn[k2-K][n])
__device__ float g_Bt0[(size_t)256 * 256];
__device__ float g_Bt1[(size_t)256 * 512];
__device__ float g_Bt2[(size_t)64 * 512];

// ---------------- helpers ----------------
__device__ __forceinline__ uint32_t smem_u32(const void* p) {
    uint32_t a;
    asm("{ .reg .u64 t; cvta.to.shared.u64 t, %1; cvt.u32.u64 %0, t; }"
        : "=r"(a) : "l"(p));
    return a;
}

__device__ __forceinline__ void cp16(uint32_t dst, const float* src, int sz) {
    asm volatile("cp.async.cg.shared.global [%0], [%1], 16, %2;"
                 :: "r"(dst), "l"(src), "r"(sz));
}

__device__ __forceinline__ uint32_t f2tf32(float f) {
    uint32_t r;
    asm("cvt.rna.tf32.f32 %0, %1;" : "=r"(r) : "f"(f));
    return r;
}

__device__ __forceinline__ void mma_tf32(float* c, const uint32_t* a, const uint32_t* b) {
    asm volatile(
        "mma.sync.aligned.m16n8k8.row.col.f32.tf32.tf32.f32 "
        "{%0,%1,%2,%3}, {%4,%5,%6,%7}, {%8,%9}, {%0,%1,%2,%3};"
        : "+f"(c[0]), "+f"(c[1]), "+f"(c[2]), "+f"(c[3])
        : "r"(a[0]), "r"(a[1]), "r"(a[2]), "r"(a[3]), "r"(b[0]), "r"(b[1]));
}

// ---------------- batched Bt build + cnt zero (one launch) ----------------
// bt seg sizes: L0 256*256=65536, L1 256*512=131072, L2 64*512=32768 -> 229376
__global__ void build_bt_zero_kernel(const float* __restrict__ Ws0, const float* __restrict__ Wn0,
                                     const float* __restrict__ Ws1, const float* __restrict__ Wn1,
                                     const float* __restrict__ Ws2, const float* __restrict__ Wn2) {
    long long i = (long long)blockIdx.x * blockDim.x + threadIdx.x;
    // zero cnt arrays (NTOT = 124096 <= 229376 grid coverage)
    if (i < NDST0) g_cnt0[i] = 0;
    else if (i < NDST0 + NDST1) g_cnt1[i - NDST0] = 0;
    else if (i < NTOT) g_cnt2[i - NDST0 - NDST1] = 0;

    if (i >= 65536 + 131072 + 32768) return;
    const float *Ws, *Wn; float* Bt; int K, N_out; long long j;
    if (i < 65536)               { Ws = Ws0; Wn = Wn0; Bt = g_Bt0; K = 128; N_out = 256; j = i; }
    else if (i < 65536 + 131072) { Ws = Ws1; Wn = Wn1; Bt = g_Bt1; K = 256; N_out = 256; j = i - 65536; }
    else                         { Ws = Ws2; Wn = Wn2; Bt = g_Bt2; K = 256; N_out = 47;  j = i - 65536 - 131072; }
    int K2 = 2 * K;
    int n = (int)(j / K2);
    int k2 = (int)(j % K2);
    float v = 0.f;
    if (n < N_out)
        v = (k2 < K) ? Ws[(size_t)k2 * N_out + n] : Wn[(size_t)(k2 - K) * N_out + n];
    Bt[j] = v;
}

// ---------------- batched CSR build ----------------
__global__ void hist_all_kernel(const int* __restrict__ d0, const int* __restrict__ d1,
                                const int* __restrict__ d2) {
    int i = blockIdx.x * blockDim.x + threadIdx.x;
    if (i < NE0) atomicAdd(&g_cnt0[d0[i]], 1);
    else if (i < NE0 + NE1) atomicAdd(&g_cnt1[d1[i - NE0]], 1);
    else if (i < ETOT) atomicAdd(&g_cnt2[d2[i - NE0 - NE1]], 1);
}

// per-256-block sums, 486 blocks across the 3 layers
__global__ void scan1_all_kernel() {
    const int* cnt; int* bsum; int n; int lb;
    int b = blockIdx.x;
    if (b < NB0)            { cnt = g_cnt0; bsum = g_bsum0; n = NDST0; lb = b; }
    else if (b < NB0 + NB1) { cnt = g_cnt1; bsum = g_bsum1; n = NDST1; lb = b - NB0; }
    else                    { cnt = g_cnt2; bsum = g_bsum2; n = NDST2; lb = b - NB0 - NB1; }
    __shared__ int s[8];
    int i = lb * 256 + threadIdx.x;
    int v = (i < n) ? cnt[i] : 0;
    #pragma unroll
    for (int o = 16; o; o >>= 1) v += __shfl_down_sync(~0u, v, o);
    if ((threadIdx.x & 31) == 0) s[threadIdx.x >> 5] = v;
    __syncthreads();
    if (threadIdx.x < 8) {
        int x = s[threadIdx.x];
        #pragma unroll
        for (int o = 4; o; o >>= 1) x += __shfl_down_sync(0xff, x, o);
        if (threadIdx.x == 0) bsum[lb] = x;
    }
}

// exclusive scan of block sums; one block per layer
__global__ void scan2_all_kernel() {
    int* bsum; int nb;
    if (blockIdx.x == 0)      { bsum = g_bsum0; nb = NB0; }
    else if (blockIdx.x == 1) { bsum = g_bsum1; nb = NB1; }
    else                      { bsum = g_bsum2; nb = NB2; }
    __shared__ int s[512];
    int t = threadIdx.x;
    int v = (t < nb) ? bsum[t] : 0;
    s[t] = v;
    __syncthreads();
    for (int o = 1; o < 512; o <<= 1) {
        int u = (t >= o) ? s[t - o] : 0;
        __syncthreads();
        s[t] += u;
        __syncthreads();
    }
    if (t < nb) bsum[t] = s[t] - v;   // exclusive
}

// per-block exclusive scan + offset -> rowptr, cur; 486 blocks
__global__ void scan3_all_kernel() {
    const int* cnt; const int* bsum; int* rowptr; int* cur; int n; int E; int lb;
    int b = blockIdx.x;
    if (b < NB0)            { cnt = g_cnt0; bsum = g_bsum0; rowptr = g_rp0; cur = g_cur0;
                              n = NDST0; E = NE0; lb = b; }
    else if (b < NB0 + NB1) { cnt = g_cnt1; bsum = g_bsum1; rowptr = g_rp1; cur = g_cur1;
                              n = NDST1; E = NE1; lb = b - NB0; }
    else                    { cnt = g_cnt2; bsum = g_bsum2; rowptr = g_rp2; cur = g_cur2;
                              n = NDST2; E = NE2; lb = b - NB0 - NB1; }
    __shared__ int s[256];
    int t = threadIdx.x;
    int i = lb * 256 + t;
    int v = (i < n) ? cnt[i] : 0;
    s[t] = v;
    __syncthreads();
    for (int o = 1; o < 256; o <<= 1) {
        int u = (t >= o) ? s[t - o] : 0;
        __syncthreads();
        s[t] += u;
        __syncthreads();
    }
    int ex = s[t] - v + bsum[lb];
    if (i < n) { rowptr[i] = ex; cur[i] = ex; }
    if (i == 0) rowptr[n] = E;
}

__global__ void fillidx_all_kernel(const int* __restrict__ s0, const int* __restrict__ d0,
                                   const int* __restrict__ s1, const int* __restrict__ d1,
                                   const int* __restrict__ s2, const int* __restrict__ d2) {
    int i = blockIdx.x * blockDim.x + threadIdx.x;
    if (i < NE0) {
        int p = atomicAdd(&g_cur0[d0[i]], 1);
        g_eidx0[p] = s0[i];
    } else if (i < NE0 + NE1) {
        int j = i - NE0;
        int p = atomicAdd(&g_cur1[d1[j]], 1);
        g_eidx1[p] = s1[j];
    } else if (i < ETOT) {
        int j = i - NE0 - NE1;
        int p = atomicAdd(&g_cur2[d2[j]], 1);
        g_eidx2[p] = s2[j];
    }
}

// ---------------- gather aggregation: one warp per dst row, 4-2-1 cascade ----------------
template<int V>
__global__ __launch_bounds__(256) void gather_agg_kernel(
    const float4* __restrict__ feat, const int* __restrict__ rowptr,
    const int* __restrict__ eidx, float4* __restrict__ agg, int n_dst)
{
    int w = (blockIdx.x * blockDim.x + threadIdx.x) >> 5;
    if (w >= n_dst) return;
    int lane = threadIdx.x & 31;
    int beg = rowptr[w], end = rowptr[w + 1];

    float4 acc[V];
    #pragma unroll
    for (int v = 0; v < V; v++) acc[v] = make_float4(0.f, 0.f, 0.f, 0.f);

    int j = beg;
    // quad step: 4 independent row loads in flight
    for (; j + 3 < end; j += 4) {
        int s0 = eidx[j], s1 = eidx[j + 1], s2 = eidx[j + 2], s3 = eidx[j + 3];
        #pragma unroll
        for (int v = 0; v < V; v++) {
            float4 f0 = feat[(size_t)s0 * (32 * V) + v * 32 + lane];
            float4 f1 = feat[(size_t)s1 * (32 * V) + v * 32 + lane];
            float4 f2 = feat[(size_t)s2 * (32 * V) + v * 32 + lane];
            float4 f3 = feat[(size_t)s3 * (32 * V) + v * 32 + lane];
            acc[v].x += (f0.x + f1.x) + (f2.x + f3.x);
            acc[v].y += (f0.y + f1.y) + (f2.y + f3.y);
            acc[v].z += (f0.z + f1.z) + (f2.z + f3.z);
            acc[v].w += (f0.w + f1.w) + (f2.w + f3.w);
        }
    }
    // dual step
    if (j + 1 < end) {
        int s0 = eidx[j], s1 = eidx[j + 1];
        #pragma unroll
        for (int v = 0; v < V; v++) {
            float4 f0 = feat[(size_t)s0 * (32 * V) + v * 32 + lane];
            float4 f1 = feat[(size_t)s1 * (32 * V) + v * 32 + lane];
            acc[v].x += f0.x + f1.x;
            acc[v].y += f0.y + f1.y;
            acc[v].z += f0.z + f1.z;
            acc[v].w += f0.w + f1.w;
        }
        j += 2;
    }
    // single step
    if (j < end) {
        int s0 = eidx[j];
        #pragma unroll
        for (int v = 0; v < V; v++) {
            float4 f0 = feat[(size_t)s0 * (32 * V) + v * 32 + lane];
            acc[v].x += f0.x; acc[v].y += f0.y; acc[v].z += f0.z; acc[v].w += f0.w;
        }
    }

    float inv = 1.0f / (float)max(end - beg, 1);
    #pragma unroll
    for (int v = 0; v < V; v++) {
        float4 o;
        o.x = acc[v].x * inv; o.y = acc[v].y * inv;
        o.z = acc[v].z * inv; o.w = acc[v].w * inv;
        agg[(size_t)w * (32 * V) + v * 32 + lane] = o;
    }
}

// ---------------- mma.sync tf32 fused SAGE GEMM (R6-exact) ----------------
#define LDS_P 36

template<int NPAD>
__global__ __launch_bounds__(256, 1) void sage_gemm_mma(
    const float* __restrict__ Adst, const float* __restrict__ Agg,
    const float* __restrict__ Bt, const float* __restrict__ bias,
    float* __restrict__ out, int M, int K, int N_out, int relu)
{
    constexpr int NT = NPAD / 32;
    extern __shared__ float smem[];
    float* AsBase = smem;
    float* BsBase = smem + 2 * 128 * LDS_P;

    const uint32_t sb = smem_u32(smem);
    const uint32_t sb_b = sb + 2u * 128u * LDS_P * 4u;
    const int tid = threadIdx.x;
    const int wid = tid >> 5, lane = tid & 31;
    const int g = lane >> 2, tg = lane & 3;
    const int wm = wid & 1, wn = wid >> 1;
    const int m0 = blockIdx.x * 128;
    const int K2 = 2 * K;
    const int nc = K2 / 32;

    float acc[4][NT][4];
    #pragma unroll
    for (int m = 0; m < 4; m++)
        #pragma unroll
        for (int n = 0; n < NT; n++)
            #pragma unroll
            for (int j = 0; j < 4; j++) acc[m][n][j] = 0.f;

    auto issue = [&](int ic) {
        const int buf = ic & 1;
        const int kb_b = ic * 32;
        int kb = kb_b;
        const float* __restrict__ Ap = Adst;
        if (kb >= K) { Ap = Agg; kb -= K; }
        #pragma unroll
        for (int t = 0; t < 4; t++) {
            int idx = tid + t * 256;
            int r = idx >> 3, q = idx & 7;
            int gr = m0 + r;
            int grc = gr < M ? gr : (M - 1);
            const float* src = Ap + (size_t)grc * K + kb + q * 4;
            uint32_t dst = sb + (uint32_t)((buf * 128 + r) * LDS_P + q * 4) * 4u;
            cp16(dst, src, gr < M ? 16 : 0);
        }
        #pragma unroll
        for (int t = 0; t < NPAD / 32; t++) {
            int idx = tid + t * 256;
            int n = idx >> 3, q = idx & 7;
            const float* src = Bt + (size_t)n * K2 + kb_b + q * 4;
            uint32_t dst = sb_b + (uint32_t)((buf * NPAD + n) * LDS_P + q * 4) * 4u;
            cp16(dst, src, 16);
        }
        asm volatile("cp.async.commit_group;" ::: "memory");
    };

    issue(0);
    for (int ic = 0; ic < nc; ic++) {
        if (ic + 1 < nc) {
            issue(ic + 1);
            asm volatile("cp.async.wait_group 1;" ::: "memory");
        } else {
            asm volatile("cp.async.wait_group 0;" ::: "memory");
        }
        __syncthreads();

        const float* a_ = AsBase + (ic & 1) * 128 * LDS_P;
        const float* b_ = BsBase + (ic & 1) * NPAD * LDS_P;

        #pragma unroll
        for (int s = 0; s < 4; s++) {
            const int c = s * 8 + tg;
            uint32_t af[4][4];
            #pragma unroll
            for (int m = 0; m < 4; m++) {
                int r = wm * 64 + m * 16 + g;
                af[m][0] = f2tf32(a_[r * LDS_P + c]);
                af[m][1] = f2tf32(a_[(r + 8) * LDS_P + c]);
                af[m][2] = f2tf32(a_[r * LDS_P + c + 4]);
                af[m][3] = f2tf32(a_[(r + 8) * LDS_P + c + 4]);
            }
            uint32_t bf[NT][2];
            #pragma unroll
            for (int n = 0; n < NT; n++) {
                int nn = wn * (NPAD / 4) + n * 8 + g;
                bf[n][0] = f2tf32(b_[nn * LDS_P + c]);
                bf[n][1] = f2tf32(b_[nn * LDS_P + c + 4]);
            }
            #pragma unroll
            for (int m = 0; m < 4; m++)
                #pragma unroll
                for (int n = 0; n < NT; n++)
                    mma_tf32(acc[m][n], af[m], bf[n]);
        }
        __syncthreads();
    }

    #pragma unroll
    for (int m = 0; m < 4; m++) {
        const int r0 = m0 + wm * 64 + m * 16 + g;
        #pragma unroll
        for (int n = 0; n < NT; n++) {
            const int c0 = wn * (NPAD / 4) + n * 8 + tg * 2;
            #pragma unroll
            for (int i = 0; i < 2; i++) {
                const int r = r0 + i * 8;
                if (r >= M) continue;
                #pragma unroll
                for (int j = 0; j < 2; j++) {
                    const int cc = c0 + j;
                    if (cc >= N_out) continue;
                    float v = acc[m][n][i * 2 + j] + bias[cc];
                    if (relu) v = fmaxf(v, 0.f);
                    out[(size_t)r * N_out + cc] = v;
                }
            }
        }
    }
}

#define SMEM256 ((2 * 128 * LDS_P + 2 * 256 * LDS_P) * 4)
#define SMEM64  ((2 * 128 * LDS_P + 2 * 64 * LDS_P) * 4)

// ---------------- host orchestration ----------------
extern "C" void kernel_launch(void* const* d_in, const int* in_sizes, int n_in,
                              void* d_out, int out_size) {
    const float* x    = (const float*)d_in[0];
    const int*   src0 = (const int*)  d_in[1];
    const int*   dst0 = (const int*)  d_in[2];
    const int*   src1 = (const int*)  d_in[3];
    const int*   dst1 = (const int*)  d_in[4];
    const int*   src2 = (const int*)  d_in[5];
    const int*   dst2 = (const int*)  d_in[6];
    const float* Ws0  = (const float*)d_in[7];
    const float* Wn0  = (const float*)d_in[8];
    const float* b0   = (const float*)d_in[9];
    const float* Ws1  = (const float*)d_in[10];
    const float* Wn1  = (const float*)d_in[11];
    const float* b1   = (const float*)d_in[12];
    const float* Ws2  = (const float*)d_in[13];
    const float* Wn2  = (const float*)d_in[14];
    const float* b2   = (const float*)d_in[15];
    float* out = (float*)d_out;

    float *agg0, *h1, *agg1, *h2, *agg2, *bt0, *bt1, *bt2;
    int *rp0, *rp1, *rp2, *ei0, *ei1, *ei2;
    cudaGetSymbolAddress((void**)&agg0, g_agg0);
    cudaGetSymbolAddress((void**)&h1,   g_h1);
    cudaGetSymbolAddress((void**)&agg1, g_agg1);
    cudaGetSymbolAddress((void**)&h2,   g_h2);
    cudaGetSymbolAddress((void**)&agg2, g_agg2);
    cudaGetSymbolAddress((void**)&rp0, g_rp0);
    cudaGetSymbolAddress((void**)&rp1, g_rp1);
    cudaGetSymbolAddress((void**)&rp2, g_rp2);
    cudaGetSymbolAddress((void**)&ei0, g_eidx0);
    cudaGetSymbolAddress((void**)&ei1, g_eidx1);
    cudaGetSymbolAddress((void**)&ei2, g_eidx2);
    cudaGetSymbolAddress((void**)&bt0, g_Bt0);
    cudaGetSymbolAddress((void**)&bt1, g_Bt1);
    cudaGetSymbolAddress((void**)&bt2, g_Bt2);

    cudaFuncSetAttribute(sage_gemm_mma<256>,
                         cudaFuncAttributeMaxDynamicSharedMemorySize, SMEM256);
    cudaFuncSetAttribute(sage_gemm_mma<64>,
                         cudaFuncAttributeMaxDynamicSharedMemorySize, SMEM64);

    const int TB = 256;
    const int BT_TOT = 65536 + 131072 + 32768;

    // ---- batched Bt build + cnt zero (one launch) ----
    build_bt_zero_kernel<<<(BT_TOT + TB - 1) / TB, TB>>>(Ws0, Wn0, Ws1, Wn1, Ws2, Wn2);

    // ---- batched CSR build for ALL layers ----
    hist_all_kernel<<<(ETOT + TB - 1) / TB, TB>>>(dst0, dst1, dst2);
    scan1_all_kernel<<<NBT, TB>>>();
    scan2_all_kernel<<<3, 512>>>();
    scan3_all_kernel<<<NBT, TB>>>();
    fillidx_all_kernel<<<(ETOT + TB - 1) / TB, TB>>>(src0, dst0, src1, dst1, src2, dst2);

    // ---- layer 0: x[300000,128] -> h1[100000,256], relu ----
    gather_agg_kernel<1><<<(NDST0 * 32 + TB - 1) / TB, TB>>>(
        (const float4*)x, rp0, ei0, (float4*)agg0, NDST0);
    sage_gemm_mma<256><<<(NDST0 + 127) / 128, 256, SMEM256>>>(
        x, agg0, bt0, b0, h1, NDST0, D_IN, 256, 1);

    // ---- layer 1: h1[100000,256] -> h2[20000,256], relu ----
    gather_agg_kernel<2><<<(NDST1 * 32 + TB - 1) / TB, TB>>>(
        (const float4*)h1, rp1, ei1, (float4*)agg1, NDST1);
    sage_gemm_mma<256><<<(NDST1 + 127) / 128, 256, SMEM256>>>(
        h1, agg1, bt1, b1, h2, NDST1, D_H, 256, 1);

    // ---- layer 2: h2[20000,256] -> out[4096,47], no relu ----
    gather_agg_kernel<2><<<(NDST2 * 32 + TB - 1) / TB, TB>>>(
        (const float4*)h2, rp2, ei2, (float4*)agg2, NDST2);
    sage_gemm_mma<64><<<(NDST2 + 127) / 128, 256, SMEM64>>>(
        h2, agg2, bt2, b2, out, NDST2, D_H, 47, 0);
}

// round 12
// speedup vs baseline: 1.3816x; 1.3816x over previous
#include <cuda_runtime.h>
#include <cstdint>

// ---------------- problem constants ----------------
#define NDST0  100000
#define NDST1  20000
#define NDST2  4096
#define NE0    1000000
#define NE1    300000
#define NE2    61440
#define D_IN   128
#define D_H    256
#define D_OUT  47

#define NB0 ((NDST0 + 255) / 256)   // 391
#define NB1 ((NDST1 + 255) / 256)   // 79
#define NB2 ((NDST2 + 255) / 256)   // 16
#define NBT (NB0 + NB1 + NB2)       // 486
#define ETOT (NE0 + NE1 + NE2)      // 1361440

// ---------------- scratch (device globals: allocation-free) ----------------
__device__ float g_agg0[(size_t)NDST0 * D_IN];
__device__ float g_h1[(size_t)NDST0 * D_H];
__device__ float g_agg1[(size_t)NDST1 * D_H];
__device__ float g_h2[(size_t)NDST1 * D_H];
__device__ float g_agg2[(size_t)NDST2 * D_H];
// per-layer CSR buffers
__device__ int g_cnt0[NDST0];
__device__ int g_cnt1[NDST1];
__device__ int g_cnt2[NDST2];
__device__ int g_rp0[NDST0 + 1];
__device__ int g_rp1[NDST1 + 1];
__device__ int g_rp2[NDST2 + 1];
__device__ int g_cur0[NDST0];
__device__ int g_cur1[NDST1];
__device__ int g_cur2[NDST2];
__device__ int g_eidx0[NE0];
__device__ int g_eidx1[NE1];
__device__ int g_eidx2[NE2];
__device__ int g_bsum0[NB0];
__device__ int g_bsum1[NB1];
__device__ int g_bsum2[NB2];
// transposed/concat weights: Bt[n][k2] = (k2<K ? Ws[k2][n] : Wn[k2-K][n])
__device__ float g_Bt0[(size_t)256 * 256];
__device__ float g_Bt1[(size_t)256 * 512];
__device__ float g_Bt2[(size_t)64 * 512];

// ---------------- helpers ----------------
__device__ __forceinline__ uint32_t smem_u32(const void* p) {
    uint32_t a;
    asm("{ .reg .u64 t; cvta.to.shared.u64 t, %1; cvt.u32.u64 %0, t; }"
        : "=r"(a) : "l"(p));
    return a;
}

__device__ __forceinline__ void cp16(uint32_t dst, const float* src, int sz) {
    asm volatile("cp.async.cg.shared.global [%0], [%1], 16, %2;"
                 :: "r"(dst), "l"(src), "r"(sz));
}

__device__ __forceinline__ uint32_t f2tf32(float f) {
    uint32_t r;
    asm("cvt.rna.tf32.f32 %0, %1;" : "=r"(r) : "f"(f));
    return r;
}

__device__ __forceinline__ void mma_tf32(float* c, const uint32_t* a, const uint32_t* b) {
    asm volatile(
        "mma.sync.aligned.m16n8k8.row.col.f32.tf32.tf32.f32 "
        "{%0,%1,%2,%3}, {%4,%5,%6,%7}, {%8,%9}, {%0,%1,%2,%3};"
        : "+f"(c[0]), "+f"(c[1]), "+f"(c[2]), "+f"(c[3])
        : "r"(a[0]), "r"(a[1]), "r"(a[2]), "r"(a[3]), "r"(b[0]), "r"(b[1]));
}

// ---------------- batched CSR build (one pipeline, all 3 layers) ----------------
__global__ void zero_all_kernel() {
    int i = blockIdx.x * blockDim.x + threadIdx.x;
    if (i < NDST0) g_cnt0[i] = 0;
    else if (i < NDST0 + NDST1) g_cnt1[i - NDST0] = 0;
    else if (i < NDST0 + NDST1 + NDST2) g_cnt2[i - NDST0 - NDST1] = 0;
}

__global__ void hist_all_kernel(const int* __restrict__ d0, const int* __restrict__ d1,
                                const int* __restrict__ d2) {
    int i = blockIdx.x * blockDim.x + threadIdx.x;
    if (i < NE0) atomicAdd(&g_cnt0[d0[i]], 1);
    else if (i < NE0 + NE1) atomicAdd(&g_cnt1[d1[i - NE0]], 1);
    else if (i < ETOT) atomicAdd(&g_cnt2[d2[i - NE0 - NE1]], 1);
}

// per-256-block sums, 486 blocks across the 3 layers
__global__ void scan1_all_kernel() {
    const int* cnt; int* bsum; int n; int lb;
    int b = blockIdx.x;
    if (b < NB0)            { cnt = g_cnt0; bsum = g_bsum0; n = NDST0; lb = b; }
    else if (b < NB0 + NB1) { cnt = g_cnt1; bsum = g_bsum1; n = NDST1; lb = b - NB0; }
    else                    { cnt = g_cnt2; bsum = g_bsum2; n = NDST2; lb = b - NB0 - NB1; }
    __shared__ int s[8];
    int i = lb * 256 + threadIdx.x;
    int v = (i < n) ? cnt[i] : 0;
    #pragma unroll
    for (int o = 16; o; o >>= 1) v += __shfl_down_sync(~0u, v, o);
    if ((threadIdx.x & 31) == 0) s[threadIdx.x >> 5] = v;
    __syncthreads();
    if (threadIdx.x < 8) {
        int x = s[threadIdx.x];
        #pragma unroll
        for (int o = 4; o; o >>= 1) x += __shfl_down_sync(0xff, x, o);
        if (threadIdx.x == 0) bsum[lb] = x;
    }
}

// exclusive scan of block sums; one block per layer
__global__ void scan2_all_kernel() {
    int* bsum; int nb;
    if (blockIdx.x == 0)      { bsum = g_bsum0; nb = NB0; }
    else if (blockIdx.x == 1) { bsum = g_bsum1; nb = NB1; }
    else                      { bsum = g_bsum2; nb = NB2; }
    __shared__ int s[512];
    int t = threadIdx.x;
    int v = (t < nb) ? bsum[t] : 0;
    s[t] = v;
    __syncthreads();
    for (int o = 1; o < 512; o <<= 1) {
        int u = (t >= o) ? s[t - o] : 0;
        __syncthreads();
        s[t] += u;
        __syncthreads();
    }
    if (t < nb) bsum[t] = s[t] - v;   // exclusive
}

// per-block exclusive scan + offset -> rowptr, cur; 486 blocks
__global__ void scan3_all_kernel() {
    const int* cnt; const int* bsum; int* rowptr; int* cur; int n; int E; int lb;
    int b = blockIdx.x;
    if (b < NB0)            { cnt = g_cnt0; bsum = g_bsum0; rowptr = g_rp0; cur = g_cur0;
                              n = NDST0; E = NE0; lb = b; }
    else if (b < NB0 + NB1) { cnt = g_cnt1; bsum = g_bsum1; rowptr = g_rp1; cur = g_cur1;
                              n = NDST1; E = NE1; lb = b - NB0; }
    else                    { cnt = g_cnt2; bsum = g_bsum2; rowptr = g_rp2; cur = g_cur2;
                              n = NDST2; E = NE2; lb = b - NB0 - NB1; }
    __shared__ int s[256];
    int t = threadIdx.x;
    int i = lb * 256 + t;
    int v = (i < n) ? cnt[i] : 0;
    s[t] = v;
    __syncthreads();
    for (int o = 1; o < 256; o <<= 1) {
        int u = (t >= o) ? s[t - o] : 0;
        __syncthreads();
        s[t] += u;
        __syncthreads();
    }
    int ex = s[t] - v + bsum[lb];
    if (i < n) { rowptr[i] = ex; cur[i] = ex; }
    if (i == 0) rowptr[n] = E;
}

__global__ void fillidx_all_kernel(const int* __restrict__ s0, const int* __restrict__ d0,
                                   const int* __restrict__ s1, const int* __restrict__ d1,
                                   const int* __restrict__ s2, const int* __restrict__ d2) {
    int i = blockIdx.x * blockDim.x + threadIdx.x;
    if (i < NE0) {
        int p = atomicAdd(&g_cur0[d0[i]], 1);
        g_eidx0[p] = s0[i];
    } else if (i < NE0 + NE1) {
        int j = i - NE0;
        int p = atomicAdd(&g_cur1[d1[j]], 1);
        g_eidx1[p] = s1[j];
    } else if (i < ETOT) {
        int j = i - NE0 - NE1;
        int p = atomicAdd(&g_cur2[d2[j]], 1);
        g_eidx2[p] = s2[j];
    }
}

// ---------------- gather aggregation: one warp per dst row (unroll-2, proven) ----------------
template<int V>
__global__ __launch_bounds__(256) void gather_agg_kernel(
    const float4* __restrict__ feat, const int* __restrict__ rowptr,
    const int* __restrict__ eidx, float4* __restrict__ agg, int n_dst)
{
    int w = (blockIdx.x * blockDim.x + threadIdx.x) >> 5;
    if (w >= n_dst) return;
    int lane = threadIdx.x & 31;
    int beg = rowptr[w], end = rowptr[w + 1];

    float4 acc[V];
    #pragma unroll
    for (int v = 0; v < V; v++) acc[v] = make_float4(0.f, 0.f, 0.f, 0.f);

    int j = beg;
    for (; j + 1 < end; j += 2) {
        int s0 = eidx[j], s1 = eidx[j + 1];
        #pragma unroll
        for (int v = 0; v < V; v++) {
            float4 f0 = feat[(size_t)s0 * (32 * V) + v * 32 + lane];
            float4 f1 = feat[(size_t)s1 * (32 * V) + v * 32 + lane];
            acc[v].x += f0.x + f1.x;
            acc[v].y += f0.y + f1.y;
            acc[v].z += f0.z + f1.z;
            acc[v].w += f0.w + f1.w;
        }
    }
    if (j < end) {
        int s0 = eidx[j];
        #pragma unroll
        for (int v = 0; v < V; v++) {
            float4 f0 = feat[(size_t)s0 * (32 * V) + v * 32 + lane];
            acc[v].x += f0.x; acc[v].y += f0.y; acc[v].z += f0.z; acc[v].w += f0.w;
        }
    }

    float inv = 1.0f / (float)max(end - beg, 1);
    #pragma unroll
    for (int v = 0; v < V; v++) {
        float4 o;
        o.x = acc[v].x * inv; o.y = acc[v].y * inv;
        o.z = acc[v].z * inv; o.w = acc[v].w * inv;
        agg[(size_t)w * (32 * V) + v * 32 + lane] = o;
    }
}

// ---------------- batched Bt build (one launch) ----------------
// seg sizes: L0 256*256=65536, L1 256*512=131072, L2 64*512=32768
__global__ void build_bt_all_kernel(const float* __restrict__ Ws0, const float* __restrict__ Wn0,
                                    const float* __restrict__ Ws1, const float* __restrict__ Wn1,
                                    const float* __restrict__ Ws2, const float* __restrict__ Wn2) {
    long long i = (long long)blockIdx.x * blockDim.x + threadIdx.x;
    const float *Ws, *Wn; float* Bt; int K, N_out; long long j;
    if (i < 65536)                 { Ws = Ws0; Wn = Wn0; Bt = g_Bt0; K = 128; N_out = 256; j = i; }
    else if (i < 65536 + 131072)   { Ws = Ws1; Wn = Wn1; Bt = g_Bt1; K = 256; N_out = 256; j = i - 65536; }
    else if (i < 65536 + 131072 + 32768)
                                   { Ws = Ws2; Wn = Wn2; Bt = g_Bt2; K = 256; N_out = 47;  j = i - 65536 - 131072; }
    else return;
    int K2 = 2 * K;
    int n = (int)(j / K2);
    int k2 = (int)(j % K2);
    float v = 0.f;
    if (n < N_out)
        v = (k2 < K) ? Ws[(size_t)k2 * N_out + n] : Wn[(size_t)(k2 - K) * N_out + n];
    Bt[j] = v;
}

// ---------------- mma.sync tf32 fused SAGE GEMM (R6-exact) ----------------
#define LDS_P 36

template<int NPAD>
__global__ __launch_bounds__(256, 1) void sage_gemm_mma(
    const float* __restrict__ Adst, const float* __restrict__ Agg,
    const float* __restrict__ Bt, const float* __restrict__ bias,
    float* __restrict__ out, int M, int K, int N_out, int relu)
{
    constexpr int NT = NPAD / 32;
    extern __shared__ float smem[];
    float* AsBase = smem;
    float* BsBase = smem + 2 * 128 * LDS_P;

    const uint32_t sb = smem_u32(smem);
    const uint32_t sb_b = sb + 2u * 128u * LDS_P * 4u;
    const int tid = threadIdx.x;
    const int wid = tid >> 5, lane = tid & 31;
    const int g = lane >> 2, tg = lane & 3;
    const int wm = wid & 1, wn = wid >> 1;
    const int m0 = blockIdx.x * 128;
    const int K2 = 2 * K;
    const int nc = K2 / 32;

    float acc[4][NT][4];
    #pragma unroll
    for (int m = 0; m < 4; m++)
        #pragma unroll
        for (int n = 0; n < NT; n++)
            #pragma unroll
            for (int j = 0; j < 4; j++) acc[m][n][j] = 0.f;

    auto issue = [&](int ic) {
        const int buf = ic & 1;
        const int kb_b = ic * 32;
        int kb = kb_b;
        const float* __restrict__ Ap = Adst;
        if (kb >= K) { Ap = Agg; kb -= K; }
        #pragma unroll
        for (int t = 0; t < 4; t++) {
            int idx = tid + t * 256;
            int r = idx >> 3, q = idx & 7;
            int gr = m0 + r;
            int grc = gr < M ? gr : (M - 1);
            const float* src = Ap + (size_t)grc * K + kb + q * 4;
            uint32_t dst = sb + (uint32_t)((buf * 128 + r) * LDS_P + q * 4) * 4u;
            cp16(dst, src, gr < M ? 16 : 0);
        }
        #pragma unroll
        for (int t = 0; t < NPAD / 32; t++) {
            int idx = tid + t * 256;
            int n = idx >> 3, q = idx & 7;
            const float* src = Bt + (size_t)n * K2 + kb_b + q * 4;
            uint32_t dst = sb_b + (uint32_t)((buf * NPAD + n) * LDS_P + q * 4) * 4u;
            cp16(dst, src, 16);
        }
        asm volatile("cp.async.commit_group;" ::: "memory");
    };

    issue(0);
    for (int ic = 0; ic < nc; ic++) {
        if (ic + 1 < nc) {
            issue(ic + 1);
            asm volatile("cp.async.wait_group 1;" ::: "memory");
        } else {
            asm volatile("cp.async.wait_group 0;" ::: "memory");
        }
        __syncthreads();

        const float* a_ = AsBase + (ic & 1) * 128 * LDS_P;
        const float* b_ = BsBase + (ic & 1) * NPAD * LDS_P;

        #pragma unroll
        for (int s = 0; s < 4; s++) {
            const int c = s * 8 + tg;
            uint32_t af[4][4];
            #pragma unroll
            for (int m = 0; m < 4; m++) {
                int r = wm * 64 + m * 16 + g;
                af[m][0] = f2tf32(a_[r * LDS_P + c]);
                af[m][1] = f2tf32(a_[(r + 8) * LDS_P + c]);
                af[m][2] = f2tf32(a_[r * LDS_P + c + 4]);
                af[m][3] = f2tf32(a_[(r + 8) * LDS_P + c + 4]);
            }
            uint32_t bf[NT][2];
            #pragma unroll
            for (int n = 0; n < NT; n++) {
                int nn = wn * (NPAD / 4) + n * 8 + g;
                bf[n][0] = f2tf32(b_[nn * LDS_P + c]);
                bf[n][1] = f2tf32(b_[nn * LDS_P + c + 4]);
            }
            #pragma unroll
            for (int m = 0; m < 4; m++)
                #pragma unroll
                for (int n = 0; n < NT; n++)
                    mma_tf32(acc[m][n], af[m], bf[n]);
        }
        __syncthreads();
    }

    #pragma unroll
    for (int m = 0; m < 4; m++) {
        const int r0 = m0 + wm * 64 + m * 16 + g;
        #pragma unroll
        for (int n = 0; n < NT; n++) {
            const int c0 = wn * (NPAD / 4) + n * 8 + tg * 2;
            #pragma unroll
            for (int i = 0; i < 2; i++) {
                const int r = r0 + i * 8;
                if (r >= M) continue;
                #pragma unroll
                for (int j = 0; j < 2; j++) {
                    const int cc = c0 + j;
                    if (cc >= N_out) continue;
                    float v = acc[m][n][i * 2 + j] + bias[cc];
                    if (relu) v = fmaxf(v, 0.f);
                    out[(size_t)r * N_out + cc] = v;
                }
            }
        }
    }
}

#define SMEM256 ((2 * 128 * LDS_P + 2 * 256 * LDS_P) * 4)
#define SMEM64  ((2 * 128 * LDS_P + 2 * 64 * LDS_P) * 4)

// ---------------- host orchestration ----------------
extern "C" void kernel_launch(void* const* d_in, const int* in_sizes, int n_in,
                              void* d_out, int out_size) {
    const float* x    = (const float*)d_in[0];
    const int*   src0 = (const int*)  d_in[1];
    const int*   dst0 = (const int*)  d_in[2];
    const int*   src1 = (const int*)  d_in[3];
    const int*   dst1 = (const int*)  d_in[4];
    const int*   src2 = (const int*)  d_in[5];
    const int*   dst2 = (const int*)  d_in[6];
    const float* Ws0  = (const float*)d_in[7];
    const float* Wn0  = (const float*)d_in[8];
    const float* b0   = (const float*)d_in[9];
    const float* Ws1  = (const float*)d_in[10];
    const float* Wn1  = (const float*)d_in[11];
    const float* b1   = (const float*)d_in[12];
    const float* Ws2  = (const float*)d_in[13];
    const float* Wn2  = (const float*)d_in[14];
    const float* b2   = (const float*)d_in[15];
    float* out = (float*)d_out;

    float *agg0, *h1, *agg1, *h2, *agg2, *bt0, *bt1, *bt2;
    int *rp0, *rp1, *rp2, *ei0, *ei1, *ei2;
    cudaGetSymbolAddress((void**)&agg0, g_agg0);
    cudaGetSymbolAddress((void**)&h1,   g_h1);
    cudaGetSymbolAddress((void**)&agg1, g_agg1);
    cudaGetSymbolAddress((void**)&h2,   g_h2);
    cudaGetSymbolAddress((void**)&agg2, g_agg2);
    cudaGetSymbolAddress((void**)&rp0, g_rp0);
    cudaGetSymbolAddress((void**)&rp1, g_rp1);
    cudaGetSymbolAddress((void**)&rp2, g_rp2);
    cudaGetSymbolAddress((void**)&ei0, g_eidx0);
    cudaGetSymbolAddress((void**)&ei1, g_eidx1);
    cudaGetSymbolAddress((void**)&ei2, g_eidx2);
    cudaGetSymbolAddress((void**)&bt0, g_Bt0);
    cudaGetSymbolAddress((void**)&bt1, g_Bt1);
    cudaGetSymbolAddress((void**)&bt2, g_Bt2);

    cudaFuncSetAttribute(sage_gemm_mma<256>,
                         cudaFuncAttributeMaxDynamicSharedMemorySize, SMEM256);
    cudaFuncSetAttribute(sage_gemm_mma<64>,
                         cudaFuncAttributeMaxDynamicSharedMemorySize, SMEM64);

    const int TB = 256;
    const int NTOT = NDST0 + NDST1 + NDST2;
    const int BT_TOT = 65536 + 131072 + 32768;

    // ---- batched CSR build for ALL layers (depends only on inputs) ----
    zero_all_kernel<<<(NTOT + TB - 1) / TB, TB>>>();
    hist_all_kernel<<<(ETOT + TB - 1) / TB, TB>>>(dst0, dst1, dst2);
    scan1_all_kernel<<<NBT, TB>>>();
    scan2_all_kernel<<<3, 512>>>();
    scan3_all_kernel<<<NBT, TB>>>();
    fillidx_all_kernel<<<(ETOT + TB - 1) / TB, TB>>>(src0, dst0, src1, dst1, src2, dst2);

    // ---- batched weight transpose ----
    build_bt_all_kernel<<<(BT_TOT + TB - 1) / TB, TB>>>(Ws0, Wn0, Ws1, Wn1, Ws2, Wn2);

    // ---- layer 0: x[300000,128] -> h1[100000,256], relu ----
    gather_agg_kernel<1><<<(NDST0 * 32 + TB - 1) / TB, TB>>>(
        (const float4*)x, rp0, ei0, (float4*)agg0, NDST0);
    sage_gemm_mma<256><<<(NDST0 + 127) / 128, 256, SMEM256>>>(
        x, agg0, bt0, b0, h1, NDST0, D_IN, 256, 1);

    // ---- layer 1: h1[100000,256] -> h2[20000,256], relu ----
    gather_agg_kernel<2><<<(NDST1 * 32 + TB - 1) / TB, TB>>>(
        (const float4*)h1, rp1, ei1, (float4*)agg1, NDST1);
    sage_gemm_mma<256><<<(NDST1 + 127) / 128, 256, SMEM256>>>(
        h1, agg1, bt1, b1, h2, NDST1, D_H, 256, 1);

    // ---- layer 2: h2[20000,256] -> out[4096,47], no relu ----
    gather_agg_kernel<2><<<(NDST2 * 32 + TB - 1) / TB, TB>>>(
        (const float4*)h2, rp2, ei2, (float4*)agg2, NDST2);
    sage_gemm_mma<64><<<(NDST2 + 127) / 128, 256, SMEM64>>>(
        h2, agg2, bt2, b2, out, NDST2, D_H, 47, 0);
}